// round 1
// baseline (speedup 1.0000x reference)
#include <cuda_runtime.h>
#include <math.h>

#define Nn   8000
#define NPc  1000
#define Bc   8
#define Fc   1000
#define HCc  32
#define Ec   80000
#define TRIc 499500
#define HIDc 128
#define EPSc 1e-5f

// ---------------- scratch (no cudaMalloc allowed) ----------------
__device__ float g_deg[Nn];
__device__ int   g_cnt[Nn];
__device__ int   g_rowptr[Nn + 1];
__device__ int   g_cursor[Nn];
__device__ int   g_csrc[Ec];
__device__ float g_csw[Ec];
__device__ float g_bufA[Nn * HCc];
__device__ float g_bufB[Nn * HCc];
__device__ float g_bufC[Nn * HCc];
__device__ float g_h[3][Nn * HCc];
__device__ float g_emb[Bc * 96];
__device__ float g_y1[Bc * HIDc];

// ---------------- graph preprocessing ----------------
__global__ void zero_kernel() {
    int i = blockIdx.x * blockDim.x + threadIdx.x;
    if (i < Nn) { g_deg[i] = 0.f; g_cnt[i] = 0; }
    if (i < Bc * HIDc) g_y1[i] = 0.f;
}

__global__ void count_kernel(const int* __restrict__ src, const int* __restrict__ dst, int E) {
    int e = blockIdx.x * blockDim.x + threadIdx.x;
    if (e >= E) return;
    atomicAdd(&g_deg[src[e]], 1.f);
    atomicAdd(&g_cnt[dst[e]], 1);
}

__global__ void scan_kernel() {
    __shared__ int part[1024];
    int t = threadIdx.x;
    int local[8];
    int s = 0;
#pragma unroll
    for (int q = 0; q < 8; q++) {
        int idx = t * 8 + q;
        int c = (idx < Nn) ? g_cnt[idx] : 0;
        local[q] = s; s += c;
    }
    part[t] = s;
    __syncthreads();
    for (int off = 1; off < 1024; off <<= 1) {
        int v = (t >= off) ? part[t - off] : 0;
        __syncthreads();
        part[t] += v;
        __syncthreads();
    }
    int pref = (t > 0) ? part[t - 1] : 0;
#pragma unroll
    for (int q = 0; q < 8; q++) {
        int idx = t * 8 + q;
        if (idx < Nn) { g_rowptr[idx] = pref + local[q]; g_cursor[idx] = pref + local[q]; }
    }
    if (t == 0) g_rowptr[Nn] = part[1023];
}

__global__ void build_kernel(const int* __restrict__ src, const int* __restrict__ dst, int E) {
    int e = blockIdx.x * blockDim.x + threadIdx.x;
    if (e >= E) return;
    int s = src[e], d = dst[e];
    float ds = g_deg[s], dd = g_deg[d];
    float w = -((ds > 0.f) ? rsqrtf(ds) : 0.f) * ((dd > 0.f) ? rsqrtf(dd) : 0.f);
    int pos = atomicAdd(&g_cursor[d], 1);
    g_csrc[pos] = s;
    g_csw[pos]  = w;
}

// ---------------- Clenshaw-Chebyshev step (fused base + prop + tanh) ----------------
// Computes T[d] = base_k(d) [+ bias] - P[d] + factor * sum_{e->d} w_e * C[src_e]
// base: mode 0 -> Wk[(d % NP) * 32 + l]  (layer 0, identity input)
//       mode 1 -> (h_in[d] @ Wk)[l]      (Wk is 32x32, cached in smem)
// flags bit0 = do prop, bit1 = tanh
__global__ void cheb_step_kernel(const float* __restrict__ Wk, const float* __restrict__ h_in,
                                 int mode,
                                 const float* __restrict__ P, const float* __restrict__ C,
                                 float* __restrict__ T,
                                 float factor, const float* __restrict__ bias, int flags) {
    __shared__ float sW[HCc * HCc];
    int t = threadIdx.x;
    if (mode == 1) {
        for (int idx = t; idx < HCc * HCc; idx += 256) sW[idx] = Wk[idx];
        __syncthreads();
    }
    int wp = t >> 5, l = t & 31;
    int d = blockIdx.x * 8 + wp;
    if (d >= Nn) return;

    float v;
    if (mode == 0) {
        v = Wk[(d % NPc) * HCc + l];
    } else {
        const float* hr = h_in + d * HCc;
        v = 0.f;
#pragma unroll
        for (int j = 0; j < HCc; j++) v = fmaf(hr[j], sW[j * HCc + l], v);
    }
    if (bias) v += bias[l];
    if (P) v -= P[d * HCc + l];
    if (flags & 1) {
        float s = 0.f;
        int i0 = g_rowptr[d], i1 = g_rowptr[d + 1];
        for (int i = i0; i < i1; i++) {
            s = fmaf(g_csw[i], C[g_csrc[i] * HCc + l], s);
        }
        v = fmaf(factor, s, v);
    }
    if (flags & 2) v = tanhf(v);
    T[d * HCc + l] = v;
}

// ---------------- pooling (mean over 1000 contiguous nodes per batch) ----------------
__global__ void pool_kernel() {
    int blk = blockIdx.x;       // 24 blocks: b*3 + layer
    int b = blk / 3, L = blk % 3;
    const float* h = g_h[L];
    int wp = threadIdx.x >> 5, l = threadIdx.x & 31;
    float acc = 0.f;
    for (int i = wp; i < NPc; i += 8) acc += h[(b * NPc + i) * HCc + l];
    __shared__ float red[8][32];
    red[wp][l] = acc;
    __syncthreads();
    if (wp == 0) {
        float s = 0.f;
#pragma unroll
        for (int q = 0; q < 8; q++) s += red[q][l];
        g_emb[b * 96 + L * 32 + l] = s * (1.f / (float)NPc);
    }
}

// ---------------- hbn (BN over 8 samples, 96 cols) -> d_out[16:784] ----------------
__global__ void hbn_kernel(const float* __restrict__ g, const float* __restrict__ be,
                           float* __restrict__ outh) {
    int c = threadIdx.x;
    if (c >= 96) return;
    float m = 0.f;
#pragma unroll
    for (int b = 0; b < 8; b++) m += g_emb[b * 96 + c];
    m *= 0.125f;
    float v = 0.f;
#pragma unroll
    for (int b = 0; b < 8; b++) { float d = g_emb[b * 96 + c] - m; v = fmaf(d, d, v); }
    v *= 0.125f;
    float sc = rsqrtf(v + EPSc) * g[c];
#pragma unroll
    for (int b = 0; b < 8; b++) outh[b * 96 + c] = (g_emb[b * 96 + c] - m) * sc + be[c];
}

// ---------------- fused triu-extract + feature-BN + big GEMM ----------------
// y1[b][h] = sum_t fbn(t,b) * W1[t][h]; fbn = BN over the 8 samples of feats.
__global__ __launch_bounds__(256) void feat_gemm_kernel(const float* __restrict__ x,
                                                        const float* __restrict__ W1,
                                                        const float* __restrict__ bng,
                                                        const float* __restrict__ bnb) {
    __shared__ float sfb[256 * 9];
    __shared__ float sred[Bc * HIDc];
    int t = threadIdx.x;
    int wp = t >> 5, l = t & 31;
    float acc[8][4];
#pragma unroll
    for (int b = 0; b < 8; b++)
#pragma unroll
        for (int q = 0; q < 4; q++) acc[b][q] = 0.f;

    int nchunk = (TRIc + 255) / 256;
    for (int ch = blockIdx.x; ch < nchunk; ch += gridDim.x) {
        int f = ch * 256 + t;
        if (f < TRIc) {
            // invert upper-triangular linear index: S(i) = i*(1999-i)/2 <= f < S(i+1)
            float disc = 3996001.0f - 8.0f * (float)f;
            float sq = sqrtf(fmaxf(disc, 0.f));
            int i = (int)((1999.0f - sq) * 0.5f);
            if (i < 0) i = 0;
            if (i > Fc - 2) i = Fc - 2;
            while (i + 1 <= Fc - 2 && (((long long)(i + 1) * (1999 - (i + 1))) >> 1) <= (long long)f) i++;
            while (i > 0 && (((long long)i * (1999 - i)) >> 1) > (long long)f) i--;
            int Si = (int)(((long long)i * (1999 - i)) >> 1);
            int j = i + 1 + (f - Si);

            float v[8];
            float m = 0.f;
#pragma unroll
            for (int b = 0; b < 8; b++) {
                v[b] = x[(size_t)(b * Fc + i) * Fc + j];
                m += v[b];
            }
            m *= 0.125f;
            float var = 0.f;
#pragma unroll
            for (int b = 0; b < 8; b++) { float d = v[b] - m; var = fmaf(d, d, var); }
            var *= 0.125f;
            float sc = rsqrtf(var + EPSc) * bng[f];
            float sh = bnb[f];
#pragma unroll
            for (int b = 0; b < 8; b++) sfb[t * 9 + b] = (v[b] - m) * sc + sh;
        } else {
#pragma unroll
            for (int b = 0; b < 8; b++) sfb[t * 9 + b] = 0.f;
        }
        __syncthreads();

        int fbase = ch * 256 + wp * 32;
        for (int ff = 0; ff < 32; ff++) {
            int f2 = fbase + ff;
            if (f2 >= TRIc) break;
            const float4 wr = *reinterpret_cast<const float4*>(W1 + (size_t)f2 * HIDc + l * 4);
            int sb = (wp * 32 + ff) * 9;
#pragma unroll
            for (int b = 0; b < 8; b++) {
                float fb = sfb[sb + b];
                acc[b][0] = fmaf(fb, wr.x, acc[b][0]);
                acc[b][1] = fmaf(fb, wr.y, acc[b][1]);
                acc[b][2] = fmaf(fb, wr.z, acc[b][2]);
                acc[b][3] = fmaf(fb, wr.w, acc[b][3]);
            }
        }
        __syncthreads();
    }

    // block reduction into smem, then sparse global atomics
    for (int idx = t; idx < Bc * HIDc; idx += 256) sred[idx] = 0.f;
    __syncthreads();
#pragma unroll
    for (int b = 0; b < 8; b++)
#pragma unroll
        for (int q = 0; q < 4; q++)
            atomicAdd(&sred[b * HIDc + l * 4 + q], acc[b][q]);
    __syncthreads();
    for (int idx = t; idx < Bc * HIDc; idx += 256) atomicAdd(&g_y1[idx], sred[idx]);
}

// ---------------- small MLP head (single block) -> d_out[0:16] ----------------
__global__ void mlp_kernel(const float* __restrict__ b1,
                           const float* __restrict__ g1, const float* __restrict__ be1,
                           const float* __restrict__ W2, const float* __restrict__ b2,
                           const float* __restrict__ g2, const float* __restrict__ be2,
                           const float* __restrict__ W3, const float* __restrict__ b3,
                           const float* __restrict__ g3, const float* __restrict__ be3,
                           const float* __restrict__ W4, const float* __restrict__ b4,
                           float* __restrict__ out) {
    __shared__ float a1[8 * 128];
    __shared__ float a2[8 * 64];
    __shared__ float a3[8 * 64];
    __shared__ float lg[16];
    int t = threadIdx.x;

    for (int idx = t; idx < 1024; idx += 256) a1[idx] = g_y1[idx] + b1[idx & 127];
    __syncthreads();
    if (t < 128) {
        float m = 0.f;
#pragma unroll
        for (int b = 0; b < 8; b++) m += a1[b * 128 + t];
        m *= 0.125f;
        float v = 0.f;
#pragma unroll
        for (int b = 0; b < 8; b++) { float d = a1[b * 128 + t] - m; v = fmaf(d, d, v); }
        v *= 0.125f;
        float sc = rsqrtf(v + EPSc) * g1[t];
#pragma unroll
        for (int b = 0; b < 8; b++) {
            float z = (a1[b * 128 + t] - m) * sc + be1[t];
            a1[b * 128 + t] = z > 0.f ? z : 0.f;
        }
    }
    __syncthreads();

    for (int idx = t; idx < 512; idx += 256) {
        int b = idx >> 6, h = idx & 63;
        float s = b2[h];
        for (int j = 0; j < 128; j++) s = fmaf(a1[b * 128 + j], W2[j * 64 + h], s);
        a2[idx] = s;
    }
    __syncthreads();
    if (t < 64) {
        float m = 0.f;
#pragma unroll
        for (int b = 0; b < 8; b++) m += a2[b * 64 + t];
        m *= 0.125f;
        float v = 0.f;
#pragma unroll
        for (int b = 0; b < 8; b++) { float d = a2[b * 64 + t] - m; v = fmaf(d, d, v); }
        v *= 0.125f;
        float sc = rsqrtf(v + EPSc) * g2[t];
#pragma unroll
        for (int b = 0; b < 8; b++) {
            float z = (a2[b * 64 + t] - m) * sc + be2[t];
            a2[b * 64 + t] = z > 0.f ? z : 0.f;
        }
    }
    __syncthreads();

    for (int idx = t; idx < 512; idx += 256) {
        int b = idx >> 6, h = idx & 63;
        float s = b3[h];
        for (int j = 0; j < 64; j++) s = fmaf(a2[b * 64 + j], W3[j * 64 + h], s);
        a3[idx] = s;
    }
    __syncthreads();
    if (t < 64) {
        float m = 0.f;
#pragma unroll
        for (int b = 0; b < 8; b++) m += a3[b * 64 + t];
        m *= 0.125f;
        float v = 0.f;
#pragma unroll
        for (int b = 0; b < 8; b++) { float d = a3[b * 64 + t] - m; v = fmaf(d, d, v); }
        v *= 0.125f;
        float sc = rsqrtf(v + EPSc) * g3[t];
#pragma unroll
        for (int b = 0; b < 8; b++) {
            float z = (a3[b * 64 + t] - m) * sc + be3[t];
            a3[b * 64 + t] = z > 0.f ? z : 0.f;
        }
    }
    __syncthreads();

    if (t < 16) {
        int b = t >> 1, c = t & 1;
        float s = b4[c];
        for (int j = 0; j < 64; j++) s = fmaf(a3[b * 64 + j], W4[j * 2 + c], s);
        lg[t] = s;
    }
    __syncthreads();
    if (t < 8) {
        float l0 = lg[t * 2], l1 = lg[t * 2 + 1];
        float m = fmaxf(l0, l1);
        float lse = m + logf(expf(l0 - m) + expf(l1 - m));
        out[t * 2 + 0] = l0 - lse;
        out[t * 2 + 1] = l1 - lse;
    }
}

// ---------------- host driver ----------------
extern "C" void kernel_launch(void* const* d_in, const int* in_sizes, int n_in,
                              void* d_out, int out_size) {
    const float* x    = (const float*)d_in[0];
    const int*   ei   = (const int*)d_in[1];
    int E = in_sizes[1] / 2;
    const int* src = ei;
    const int* dst = ei + E;
    const float* cw0  = (const float*)d_in[3];
    const float* cb0  = (const float*)d_in[4];
    const float* cw1  = (const float*)d_in[5];
    const float* cb1  = (const float*)d_in[6];
    const float* cw2  = (const float*)d_in[7];
    const float* cb2  = (const float*)d_in[8];
    const float* bnhg = (const float*)d_in[9];
    const float* bnhb = (const float*)d_in[10];
    const float* bng  = (const float*)d_in[11];
    const float* bnb  = (const float*)d_in[12];
    const float* w1   = (const float*)d_in[13];
    const float* b1   = (const float*)d_in[14];
    const float* g1   = (const float*)d_in[15];
    const float* be1  = (const float*)d_in[16];
    const float* W2   = (const float*)d_in[17];
    const float* b2   = (const float*)d_in[18];
    const float* g2   = (const float*)d_in[19];
    const float* be2  = (const float*)d_in[20];
    const float* W3   = (const float*)d_in[21];
    const float* b3   = (const float*)d_in[22];
    const float* g3   = (const float*)d_in[23];
    const float* be3  = (const float*)d_in[24];
    const float* W4   = (const float*)d_in[25];
    const float* b4   = (const float*)d_in[26];
    float* out = (float*)d_out;

    float *bufA, *bufB, *bufC, *hbase;
    cudaGetSymbolAddress((void**)&bufA, g_bufA);
    cudaGetSymbolAddress((void**)&bufB, g_bufB);
    cudaGetSymbolAddress((void**)&bufC, g_bufC);
    cudaGetSymbolAddress((void**)&hbase, g_h);
    float* hs[3] = { hbase, hbase + Nn * HCc, hbase + 2 * Nn * HCc };
    float* bufs[3] = { bufA, bufB, bufC };

    // preprocessing
    zero_kernel<<<(Nn + 255) / 256, 256>>>();
    count_kernel<<<(E + 255) / 256, 256>>>(src, dst, E);
    scan_kernel<<<1, 1024>>>();
    build_kernel<<<(E + 255) / 256, 256>>>(src, dst, E);

    // big fused GEMM (independent of graph part; launch early)
    feat_gemm_kernel<<<592, 256>>>(x, w1, bng, bnb);

    const float* cws[3] = { cw0, cw1, cw2 };
    const float* cbs[3] = { cb0, cb1, cb2 };
    int grid = Nn / 8;  // 1000 blocks, warp per node

    for (int L = 0; L < 3; L++) {
        int mode = (L == 0) ? 0 : 1;
        const float* hin = (L == 0) ? nullptr : hs[L - 1];
        int stride = (L == 0) ? (Fc * HCc) : (HCc * HCc);
        const float* W = cws[L];

        // Clenshaw: b5=0; b4=v4; b_k = v_k + 2 L b_{k+1} - b_{k+2}; out = v0 + L b1 - b2
        int pi = -1, ci = 0, nexti = 1;
        cheb_step_kernel<<<grid, 256>>>(W + 4 * stride, hin, mode,
                                        nullptr, nullptr, bufs[ci], 0.f, nullptr, 0);
        for (int k = 3; k >= 1; k--) {
            int ti = nexti;
            cheb_step_kernel<<<grid, 256>>>(W + k * stride, hin, mode,
                                            (pi >= 0) ? bufs[pi] : nullptr, bufs[ci], bufs[ti],
                                            2.f, nullptr, 1);
            nexti = (pi >= 0) ? pi : 2;
            pi = ci; ci = ti;
        }
        cheb_step_kernel<<<grid, 256>>>(W + 0 * stride, hin, mode,
                                        bufs[pi], bufs[ci], hs[L],
                                        1.f, cbs[L], 3);
    }

    pool_kernel<<<24, 256>>>();
    hbn_kernel<<<1, 96>>>(bnhg, bnhb, out + 16);
    mlp_kernel<<<1, 256>>>(b1, g1, be1, W2, b2, g2, be2, W3, b3, g3, be3, W4, b4, out);
}

// round 2
// speedup vs baseline: 1.1630x; 1.1630x over previous
#include <cuda_runtime.h>
#include <math.h>

#define Nn   8000
#define NPc  1000
#define Bc   8
#define Fc   1000
#define HCc  32
#define Ec   80000
#define TRIc 499500
#define HIDc 128
#define EPSc 1e-5f
#define HVSTRIDE (Nn * HCc)

// ---------------- scratch ----------------
__device__ float g_deg[Nn];
__device__ int   g_cnt[Nn];
__device__ int   g_rowptr[Nn + 1];
__device__ int   g_cursor[Nn];
__device__ float2 g_cedge[Ec];          // (.x = local src idx bitcast, .y = weight)
__device__ float g_bufA[Nn * HCc];
__device__ float g_bufB[Nn * HCc];
__device__ float g_bufC[Nn * HCc];
__device__ float g_hv[5 * HVSTRIDE];    // v_k tables for next layer
__device__ float g_emb[Bc * 96];        // raw pooled sums (divide by NP later)
__device__ float g_y1[Bc * HIDc];
__device__ float g_fbn[TRIc * Bc];      // feature-BN values, [f][8]

// ---------------- preprocessing ----------------
__global__ void zero_kernel() {
    int i = blockIdx.x * blockDim.x + threadIdx.x;
    if (i < Nn) { g_deg[i] = 0.f; g_cnt[i] = 0; }
    if (i < Bc * 96) g_emb[i] = 0.f;
}

__global__ void count_kernel(const int* __restrict__ src, const int* __restrict__ dst, int E) {
    int e = blockIdx.x * blockDim.x + threadIdx.x;
    if (e >= E) return;
    atomicAdd(&g_deg[src[e]], 1.f);
    atomicAdd(&g_cnt[dst[e]], 1);
}

__global__ void scan_kernel() {
    __shared__ int part[1024];
    int t = threadIdx.x;
    int local[8];
    int s = 0;
#pragma unroll
    for (int q = 0; q < 8; q++) {
        int idx = t * 8 + q;
        int c = (idx < Nn) ? g_cnt[idx] : 0;
        local[q] = s; s += c;
    }
    part[t] = s;
    __syncthreads();
    for (int off = 1; off < 1024; off <<= 1) {
        int v = (t >= off) ? part[t - off] : 0;
        __syncthreads();
        part[t] += v;
        __syncthreads();
    }
    int pref = (t > 0) ? part[t - 1] : 0;
#pragma unroll
    for (int q = 0; q < 8; q++) {
        int idx = t * 8 + q;
        if (idx < Nn) { g_rowptr[idx] = pref + local[q]; g_cursor[idx] = pref + local[q]; }
    }
    if (t == 0) g_rowptr[Nn] = part[1023];
}

__global__ void build_kernel(const int* __restrict__ src, const int* __restrict__ dst, int E) {
    int e = blockIdx.x * blockDim.x + threadIdx.x;
    if (e >= E) return;
    int s = src[e], d = dst[e];
    float ds = g_deg[s], dd = g_deg[d];
    float w = -((ds > 0.f) ? rsqrtf(ds) : 0.f) * ((dd > 0.f) ? rsqrtf(dd) : 0.f);
    int pos = atomicAdd(&g_cursor[d], 1);
    int loc = s % NPc;                   // local index within batch
    g_cedge[pos] = make_float2(__int_as_float(loc), w);
}

// ---------------- Clenshaw gather step ----------------
// T[d] = V[vidx(d)] - P[pidx(d)] + 2 * sum_e w_e * Csrc[cidx(src_e)]
// vshift/pshift: index by (d % NP) instead of d (layer-0 weight tables).
// clocal: gather table indexed by local src idx directly; else by batch offset.
__global__ __launch_bounds__(512) void gather_step(
    const float* __restrict__ V, int vshift,
    const float* __restrict__ P, int pshift,
    const float* __restrict__ C, int clocal,
    float* __restrict__ T)
{
    int t = threadIdx.x, wp = t >> 5, l = t & 31;
    int d = blockIdx.x * 16 + wp;
    int b = d / NPc;
    int loc = d - b * NPc;

    float v = V[(vshift ? loc : d) * HCc + l];
    if (P) v -= P[(pshift ? loc : d) * HCc + l];

    const float* Cb = clocal ? C : (C + (size_t)b * NPc * HCc);
    int i0 = g_rowptr[d], i1 = g_rowptr[d + 1];
    float s = 0.f;
    for (int base = i0; base < i1; base += 32) {
        int e = base + l;
        int idx = 0; float we = 0.f;
        if (e < i1) { float2 ed = g_cedge[e]; idx = __float_as_int(ed.x); we = ed.y; }
        int n = min(32, i1 - base);
#pragma unroll 4
        for (int q = 0; q < n; q++) {
            int  si = __shfl_sync(0xFFFFFFFFu, idx, q);
            float wq = __shfl_sync(0xFFFFFFFFu, we, q);
            s = fmaf(wq, __ldg(Cb + si * HCc + l), s);
        }
    }
    T[d * HCc + l] = fmaf(2.f, s, v);
}

// ---------------- final Clenshaw step: tanh + pool + next-layer v-tables ----------------
// h[d] = tanh(V[vidx] - Pm[d] + sum_e w_e * C1[src] + bias)
// pool: atomic partial sums into g_emb; hv: hv[k][d] = h[d] @ Wnext[k]
__global__ __launch_bounds__(256) void final_step(
    const float* __restrict__ V, int vshift,
    const float* __restrict__ Pm,
    const float* __restrict__ C1,
    const float* __restrict__ bias,
    const float* __restrict__ Wnext,   // 5*32*32 or null
    float* __restrict__ hv,            // base of 5 planes or null
    int Lcol)
{
    __shared__ float sW[5 * HCc * HCc];
    __shared__ float red[8][HCc];
    int t = threadIdx.x, wp = t >> 5, l = t & 31;
    if (Wnext) {
        for (int idx = t; idx < 5 * HCc * HCc; idx += 256) sW[idx] = Wnext[idx];
        __syncthreads();
    }
    int d = blockIdx.x * 8 + wp;
    int b = d / NPc;
    int loc = d - b * NPc;

    float v = V[(vshift ? loc : d) * HCc + l] - Pm[d * HCc + l] + bias[l];

    const float* Cb = C1 + (size_t)b * NPc * HCc;
    int i0 = g_rowptr[d], i1 = g_rowptr[d + 1];
    float s = 0.f;
    for (int base = i0; base < i1; base += 32) {
        int e = base + l;
        int idx = 0; float we = 0.f;
        if (e < i1) { float2 ed = g_cedge[e]; idx = __float_as_int(ed.x); we = ed.y; }
        int n = min(32, i1 - base);
#pragma unroll 4
        for (int q = 0; q < n; q++) {
            int  si = __shfl_sync(0xFFFFFFFFu, idx, q);
            float wq = __shfl_sync(0xFFFFFFFFu, we, q);
            s = fmaf(wq, __ldg(Cb + si * HCc + l), s);
        }
    }
    float h = tanhf(v + s);

    // pooled partial sums
    red[wp][l] = h;
    __syncthreads();
    if (wp == 0) {
        float acc = 0.f;
#pragma unroll
        for (int q = 0; q < 8; q++) acc += red[q][l];
        atomicAdd(&g_emb[b * 96 + Lcol + l], acc);
    }

    // next-layer v-tables
    if (Wnext) {
        float acc[5] = {0.f, 0.f, 0.f, 0.f, 0.f};
#pragma unroll
        for (int j = 0; j < HCc; j++) {
            float hj = __shfl_sync(0xFFFFFFFFu, h, j);
#pragma unroll
            for (int k = 0; k < 5; k++)
                acc[k] = fmaf(hj, sW[k * HCc * HCc + j * HCc + l], acc[k]);
        }
#pragma unroll
        for (int k = 0; k < 5; k++)
            hv[k * HVSTRIDE + d * HCc + l] = acc[k];
    }
}

// ---------------- feature BN precompute (also zeroes y1) ----------------
__global__ void fbn_kernel(const float* __restrict__ x,
                           const float* __restrict__ bng,
                           const float* __restrict__ bnb) {
    if (blockIdx.x == 0) {
        for (int idx = threadIdx.x; idx < Bc * HIDc; idx += blockDim.x) g_y1[idx] = 0.f;
    }
    int f = blockIdx.x * blockDim.x + threadIdx.x;
    if (f >= TRIc) return;
    // invert upper-triangular linear index
    float disc = 3996001.0f - 8.0f * (float)f;
    float sq = sqrtf(fmaxf(disc, 0.f));
    int i = (int)((1999.0f - sq) * 0.5f);
    if (i < 0) i = 0;
    if (i > Fc - 2) i = Fc - 2;
    while (i + 1 <= Fc - 2 && (((long long)(i + 1) * (1999 - (i + 1))) >> 1) <= (long long)f) i++;
    while (i > 0 && (((long long)i * (1999 - i)) >> 1) > (long long)f) i--;
    int Si = (int)(((long long)i * (1999 - i)) >> 1);
    int j = i + 1 + (f - Si);

    float v[8];
    float m = 0.f;
#pragma unroll
    for (int b = 0; b < 8; b++) {
        v[b] = x[(size_t)(b * Fc + i) * Fc + j];
        m += v[b];
    }
    m *= 0.125f;
    float var = 0.f;
#pragma unroll
    for (int b = 0; b < 8; b++) { float dd = v[b] - m; var = fmaf(dd, dd, var); }
    var *= 0.125f;
    float sc = rsqrtf(var + EPSc) * bng[f];
    float sh = bnb[f];
#pragma unroll
    for (int b = 0; b < 8; b++) g_fbn[f * 8 + b] = (v[b] - m) * sc + sh;
}

// ---------------- streaming GEMM: y1[b][h] = sum_f fbn[f][b] * W1[f][h] ----------------
#define GEMM_GRID 1184
__global__ __launch_bounds__(256) void gemm_kernel(const float* __restrict__ W1) {
    __shared__ float sred[Bc * HIDc];
    int t = threadIdx.x, wid = t >> 5, l = t & 31;
    float acc[8][4];
#pragma unroll
    for (int b = 0; b < 8; b++)
#pragma unroll
        for (int q = 0; q < 4; q++) acc[b][q] = 0.f;

    const int CH = (TRIc + GEMM_GRID - 1) / GEMM_GRID;  // 422
    int f0 = blockIdx.x * CH;
    int f1 = min(f0 + CH, TRIc);
    for (int f = f0 + wid; f < f1; f += 8) {
        const float4 w = __ldg((const float4*)(W1 + (size_t)f * HIDc + l * 4));
#pragma unroll
        for (int b = 0; b < 8; b++) {
            float fb = __ldg(g_fbn + f * 8 + b);
            acc[b][0] = fmaf(fb, w.x, acc[b][0]);
            acc[b][1] = fmaf(fb, w.y, acc[b][1]);
            acc[b][2] = fmaf(fb, w.z, acc[b][2]);
            acc[b][3] = fmaf(fb, w.w, acc[b][3]);
        }
    }
    for (int idx = t; idx < Bc * HIDc; idx += 256) sred[idx] = 0.f;
    __syncthreads();
#pragma unroll
    for (int b = 0; b < 8; b++)
#pragma unroll
        for (int q = 0; q < 4; q++)
            atomicAdd(&sred[b * HIDc + l * 4 + q], acc[b][q]);
    __syncthreads();
    for (int idx = t; idx < Bc * HIDc; idx += 256) atomicAdd(&g_y1[idx], sred[idx]);
}

// ---------------- head: hbn output + MLP + log-softmax ----------------
__global__ void head_kernel(const float* __restrict__ bnhg, const float* __restrict__ bnhb,
                            const float* __restrict__ b1,
                            const float* __restrict__ g1, const float* __restrict__ be1,
                            const float* __restrict__ W2, const float* __restrict__ b2,
                            const float* __restrict__ g2, const float* __restrict__ be2,
                            const float* __restrict__ W3, const float* __restrict__ b3,
                            const float* __restrict__ g3, const float* __restrict__ be3,
                            const float* __restrict__ W4, const float* __restrict__ b4,
                            float* __restrict__ out) {
    __shared__ float a1[8 * 128];
    __shared__ float a2[8 * 64];
    __shared__ float a3[8 * 64];
    __shared__ float lg[16];
    int t = threadIdx.x;

    // hbn: BN over 8 samples of pooled embeddings -> out[16:784]
    if (t < 96) {
        float e[8];
        float m = 0.f;
#pragma unroll
        for (int b = 0; b < 8; b++) { e[b] = g_emb[b * 96 + t] * (1.f / (float)NPc); m += e[b]; }
        m *= 0.125f;
        float v = 0.f;
#pragma unroll
        for (int b = 0; b < 8; b++) { float dd = e[b] - m; v = fmaf(dd, dd, v); }
        v *= 0.125f;
        float sc = rsqrtf(v + EPSc) * bnhg[t];
#pragma unroll
        for (int b = 0; b < 8; b++) out[16 + b * 96 + t] = (e[b] - m) * sc + bnhb[t];
    }

    for (int idx = t; idx < 1024; idx += 256) a1[idx] = g_y1[idx] + b1[idx & 127];
    __syncthreads();
    if (t < 128) {
        float m = 0.f;
#pragma unroll
        for (int b = 0; b < 8; b++) m += a1[b * 128 + t];
        m *= 0.125f;
        float v = 0.f;
#pragma unroll
        for (int b = 0; b < 8; b++) { float dd = a1[b * 128 + t] - m; v = fmaf(dd, dd, v); }
        v *= 0.125f;
        float sc = rsqrtf(v + EPSc) * g1[t];
#pragma unroll
        for (int b = 0; b < 8; b++) {
            float z = (a1[b * 128 + t] - m) * sc + be1[t];
            a1[b * 128 + t] = z > 0.f ? z : 0.f;
        }
    }
    __syncthreads();

    for (int idx = t; idx < 512; idx += 256) {
        int b = idx >> 6, h = idx & 63;
        float s = b2[h];
        for (int j = 0; j < 128; j++) s = fmaf(a1[b * 128 + j], W2[j * 64 + h], s);
        a2[idx] = s;
    }
    __syncthreads();
    if (t < 64) {
        float m = 0.f;
#pragma unroll
        for (int b = 0; b < 8; b++) m += a2[b * 64 + t];
        m *= 0.125f;
        float v = 0.f;
#pragma unroll
        for (int b = 0; b < 8; b++) { float dd = a2[b * 64 + t] - m; v = fmaf(dd, dd, v); }
        v *= 0.125f;
        float sc = rsqrtf(v + EPSc) * g2[t];
#pragma unroll
        for (int b = 0; b < 8; b++) {
            float z = (a2[b * 64 + t] - m) * sc + be2[t];
            a2[b * 64 + t] = z > 0.f ? z : 0.f;
        }
    }
    __syncthreads();

    for (int idx = t; idx < 512; idx += 256) {
        int b = idx >> 6, h = idx & 63;
        float s = b3[h];
        for (int j = 0; j < 64; j++) s = fmaf(a2[b * 64 + j], W3[j * 64 + h], s);
        a3[idx] = s;
    }
    __syncthreads();
    if (t < 64) {
        float m = 0.f;
#pragma unroll
        for (int b = 0; b < 8; b++) m += a3[b * 64 + t];
        m *= 0.125f;
        float v = 0.f;
#pragma unroll
        for (int b = 0; b < 8; b++) { float dd = a3[b * 64 + t] - m; v = fmaf(dd, dd, v); }
        v *= 0.125f;
        float sc = rsqrtf(v + EPSc) * g3[t];
#pragma unroll
        for (int b = 0; b < 8; b++) {
            float z = (a3[b * 64 + t] - m) * sc + be3[t];
            a3[b * 64 + t] = z > 0.f ? z : 0.f;
        }
    }
    __syncthreads();

    if (t < 16) {
        int b = t >> 1, c = t & 1;
        float s = b4[c];
        for (int j = 0; j < 64; j++) s = fmaf(a3[b * 64 + j], W4[j * 2 + c], s);
        lg[t] = s;
    }
    __syncthreads();
    if (t < 8) {
        float l0 = lg[t * 2], l1 = lg[t * 2 + 1];
        float m = fmaxf(l0, l1);
        float lse = m + logf(expf(l0 - m) + expf(l1 - m));
        out[t * 2 + 0] = l0 - lse;
        out[t * 2 + 1] = l1 - lse;
    }
}

// ---------------- host driver ----------------
extern "C" void kernel_launch(void* const* d_in, const int* in_sizes, int n_in,
                              void* d_out, int out_size) {
    const float* x    = (const float*)d_in[0];
    const int*   ei   = (const int*)d_in[1];
    int E = in_sizes[1] / 2;
    const int* src = ei;
    const int* dst = ei + E;
    const float* cw0  = (const float*)d_in[3];
    const float* cb0  = (const float*)d_in[4];
    const float* cw1  = (const float*)d_in[5];
    const float* cb1  = (const float*)d_in[6];
    const float* cw2  = (const float*)d_in[7];
    const float* cb2  = (const float*)d_in[8];
    const float* bnhg = (const float*)d_in[9];
    const float* bnhb = (const float*)d_in[10];
    const float* bng  = (const float*)d_in[11];
    const float* bnb  = (const float*)d_in[12];
    const float* w1   = (const float*)d_in[13];
    const float* b1   = (const float*)d_in[14];
    const float* g1   = (const float*)d_in[15];
    const float* be1  = (const float*)d_in[16];
    const float* W2   = (const float*)d_in[17];
    const float* b2   = (const float*)d_in[18];
    const float* g2   = (const float*)d_in[19];
    const float* be2  = (const float*)d_in[20];
    const float* W3   = (const float*)d_in[21];
    const float* b3   = (const float*)d_in[22];
    const float* g3   = (const float*)d_in[23];
    const float* be3  = (const float*)d_in[24];
    const float* W4   = (const float*)d_in[25];
    const float* b4   = (const float*)d_in[26];
    float* out = (float*)d_out;

    float *bufA, *bufB, *bufC, *hv;
    cudaGetSymbolAddress((void**)&bufA, g_bufA);
    cudaGetSymbolAddress((void**)&bufB, g_bufB);
    cudaGetSymbolAddress((void**)&bufC, g_bufC);
    cudaGetSymbolAddress((void**)&hv,   g_hv);

    // fork the feature-MLP branch onto a second stream so the 256MB W1 stream
    // overlaps the serial Chebyshev chain
    cudaStream_t s2 = 0;
    cudaEvent_t evF = 0, evJ = 0;
    bool forked = (cudaStreamCreateWithFlags(&s2, cudaStreamNonBlocking) == cudaSuccess) &&
                  (cudaEventCreateWithFlags(&evF, cudaEventDisableTiming) == cudaSuccess) &&
                  (cudaEventCreateWithFlags(&evJ, cudaEventDisableTiming) == cudaSuccess);
    if (!forked) s2 = 0;

    if (forked) {
        cudaEventRecord(evF, 0);
        cudaStreamWaitEvent(s2, evF, 0);
    }
    fbn_kernel<<<(TRIc + 255) / 256, 256, 0, s2>>>(x, bng, bnb);
    gemm_kernel<<<GEMM_GRID, 256, 0, s2>>>(w1);
    if (forked) cudaEventRecord(evJ, s2);

    // graph preprocessing (stream 0)
    zero_kernel<<<(Nn + 255) / 256, 256>>>();
    count_kernel<<<(E + 255) / 256, 256>>>(src, dst, E);
    scan_kernel<<<1, 1024>>>();
    build_kernel<<<(E + 255) / 256, 256>>>(src, dst, E);

    // ---- Chebyshev via Clenshaw: 4 kernels per layer ----
    const int GG = Nn / 16;   // 500
    const int GF = Nn / 8;    // 1000

    // Layer 0 (identity input -> v_k tables are the conv_w0 planes, indexed d%NP)
    gather_step<<<GG, 512>>>(cw0 + 3 * Fc * HCc, 1, nullptr, 0, cw0 + 4 * Fc * HCc, 1, bufA);
    gather_step<<<GG, 512>>>(cw0 + 2 * Fc * HCc, 1, cw0 + 4 * Fc * HCc, 1, bufA, 0, bufB);
    gather_step<<<GG, 512>>>(cw0 + 1 * Fc * HCc, 1, bufA, 0, bufB, 0, bufC);
    final_step<<<GF, 256>>>(cw0, 1, bufB, bufC, cb0, cw1, hv, 0);

    // Layer 1 (v_k = g_hv planes, global-indexed)
    gather_step<<<GG, 512>>>(hv + 3 * HVSTRIDE, 0, nullptr, 0, hv + 4 * HVSTRIDE, 0, bufA);
    gather_step<<<GG, 512>>>(hv + 2 * HVSTRIDE, 0, hv + 4 * HVSTRIDE, 0, bufA, 0, bufB);
    gather_step<<<GG, 512>>>(hv + 1 * HVSTRIDE, 0, bufA, 0, bufB, 0, bufC);
    final_step<<<GF, 256>>>(hv, 0, bufB, bufC, cb1, cw2, hv, 32);

    // Layer 2
    gather_step<<<GG, 512>>>(hv + 3 * HVSTRIDE, 0, nullptr, 0, hv + 4 * HVSTRIDE, 0, bufA);
    gather_step<<<GG, 512>>>(hv + 2 * HVSTRIDE, 0, hv + 4 * HVSTRIDE, 0, bufA, 0, bufB);
    gather_step<<<GG, 512>>>(hv + 1 * HVSTRIDE, 0, bufA, 0, bufB, 0, bufC);
    final_step<<<GF, 256>>>(hv, 0, bufB, bufC, cb2, nullptr, nullptr, 64);

    // join feat branch, then head
    if (forked) cudaStreamWaitEvent(0, evJ, 0);
    head_kernel<<<1, 256>>>(bnhg, bnhb, b1, g1, be1, W2, b2, g2, be2,
                            W3, b3, g3, be3, W4, b4, out);
}